// round 15
// baseline (speedup 1.0000x reference)
#include <cuda_runtime.h>
#include <cuda_bf16.h>
#include <stdint.h>
#include <math.h>

// Problem constants
#define SS     5
#define BB     32
#define TT     25
#define TSTEP  24          // T-1 recurrence steps
#define VV     32000
#define EE     512
#define HH     1024
#define GG     3072        // 3*H
#define NROWS  (SS*TSTEP*BB)   // 3840
#define KP     (HH/2)      // 512 packed uint2 per row (hi-pair, lo-pair)
#define KPE    (EE/2)      // 256 packed uint2 per embedding row
#define NCTA   128         // persistent recurrence grid (1 CTA per 8 h-outputs)
#define JT     8           // h outputs per CTA
#define WSTRIDE 520        // smem row stride (uint2) for k_recur weight cache
#define SRS    10          // staged-GEMM smem row stride (uint2): 80B -> conflict-free LDS.128

// Pair-position permutation within each 8-pair group: slot -> (slot&3)*2 + (slot>>2).
// Puts pairs (tg, tg+4) adjacent so consumers use one 16B load per fragment pair.
__host__ __device__ __forceinline__ int permpos(int p) {
    int grp = p >> 3, slot = p & 7;
    return grp*8 + ((slot & 3)*2 + (slot >> 2));
}

// ---------------- scratch (static device globals; no allocation) ----------------
__device__ float d_gi  [(size_t)NROWS * GG];         // gi buffer (layer0, then layer1)
__device__ float d_hs0 [(size_t)NROWS * HH];         // layer0 hidden (fp32)
__device__ float d_hs1 [(size_t)NROWS * HH];         // layer1 hidden (fp32)

// packed split-bf16 (PERMUTED layout): uint2 {x = hi|hi<<16, y = lo|lo<<16}
__device__ uint2 d_xp  [(size_t)NROWS*KPE];          // embeddings packed
__device__ uint2 d_WpI0[(size_t)GG*KPE];             // W_ih0 packed
__device__ uint2 d_Wp0 [(size_t)GG*KP];              // W_hh0 packed
__device__ uint2 d_Wp1i[(size_t)GG*KP];              // W_ih1 packed
__device__ uint2 d_Wp1h[(size_t)GG*KP];              // W_hh1 packed
__device__ uint2 d_WpO [(size_t)VV*KP];              // W_out packed (131MB)
__device__ uint2 d_hs0p[(size_t)NROWS*KP];           // layer0 hidden packed
__device__ uint2 d_hs1p[(size_t)NROWS*KP];           // layer1 hidden packed
__device__ uint2 d_zrow[KP];                         // zero packed row
__device__ float d_zf  [HH];                         // zero fp32 row

// grid barrier state (separate lines)
__device__ unsigned d_cnt = 0;
__device__ unsigned d_padA[31];
__device__ unsigned d_gen = 0;

// ---------------- helpers -------------------------------------------------------
__device__ __forceinline__ uint2 packpair(float x, float y) {
    __nv_bfloat16 hx = __float2bfloat16_rn(x);
    __nv_bfloat16 hy = __float2bfloat16_rn(y);
    float rx = x - __bfloat162float(hx);
    float ry = y - __bfloat162float(hy);
    __nv_bfloat16 lx = __float2bfloat16_rn(rx);
    __nv_bfloat16 ly = __float2bfloat16_rn(ry);
    uint2 o;
    o.x = (unsigned int)__bfloat16_as_ushort(hx) | ((unsigned int)__bfloat16_as_ushort(hy) << 16);
    o.y = (unsigned int)__bfloat16_as_ushort(lx) | ((unsigned int)__bfloat16_as_ushort(ly) << 16);
    return o;
}

__device__ __forceinline__ void mma16816(float& d0, float& d1, float& d2, float& d3,
                                         unsigned int a0, unsigned int a1,
                                         unsigned int a2, unsigned int a3,
                                         unsigned int b0, unsigned int b1) {
    asm volatile(
        "mma.sync.aligned.m16n8k16.row.col.f32.bf16.bf16.f32 "
        "{%0,%1,%2,%3}, {%4,%5,%6,%7}, {%8,%9}, {%0,%1,%2,%3};\n"
        : "+f"(d0), "+f"(d1), "+f"(d2), "+f"(d3)
        : "r"(a0), "r"(a1), "r"(a2), "r"(a3), "r"(b0), "r"(b1));
}

// split-bf16 with uint4 fragments: v = {pair tg: hi,lo, pair tg+4: hi,lo} per row
// d += Ahi*Bhi + Ahi*Blo + Alo*Bhi
__device__ __forceinline__ void mma3v(float* d, uint4 v0, uint4 v1, uint4 vb) {
    mma16816(d[0], d[1], d[2], d[3], v0.x, v1.x, v0.z, v1.z, vb.x, vb.z);
    mma16816(d[0], d[1], d[2], d[3], v0.x, v1.x, v0.z, v1.z, vb.y, vb.w);
    mma16816(d[0], d[1], d[2], d[3], v0.y, v1.y, v0.w, v1.w, vb.x, vb.z);
}

// cp.async 16B
__device__ __forceinline__ void cpasync16(unsigned int saddr, const void* g) {
    asm volatile("cp.async.cg.shared.global [%0], [%1], 16;\n" :: "r"(saddr), "l"(g));
}
__device__ __forceinline__ void cpcommit() { asm volatile("cp.async.commit_group;\n"); }
__device__ __forceinline__ void cpwait1()  { asm volatile("cp.async.wait_group 1;\n"); }

// CG-style grid barrier: release-atomic arrive, acquire-poll on generation.
__device__ __forceinline__ void gbar() {
    __syncthreads();
    if (threadIdx.x == 0) {
        unsigned g;
        asm volatile("ld.relaxed.gpu.u32 %0, [%1];" : "=r"(g) : "l"(&d_gen));
        unsigned prev;
        asm volatile("atom.release.gpu.add.u32 %0, [%1], %2;"
                     : "=r"(prev) : "l"(&d_cnt), "r"(1u) : "memory");
        if (prev == NCTA - 1) {
            asm volatile("st.relaxed.gpu.u32 [%0], %1;" :: "l"(&d_cnt), "r"(0u) : "memory");
            asm volatile("st.release.gpu.u32 [%0], %1;" :: "l"(&d_gen), "r"(g + 1u) : "memory");
        } else {
            unsigned cur;
            do {
                asm volatile("ld.acquire.gpu.u32 %0, [%1];" : "=r"(cur) : "l"(&d_gen) : "memory");
            } while (cur == g);
        }
    }
    __syncthreads();
}

// ---------------- init / packing -----------------------------------------------
__global__ void k_zero_init() {
    int i = threadIdx.x;
    if (i < KP) d_zrow[i] = make_uint2(0u, 0u);
    d_zf[i] = 0.0f; d_zf[i + 512] = 0.0f;
}

// pack + permute (rows are multiples of 8 pairs, so flat grouping == per-row grouping)
__global__ void k_packw(const float* __restrict__ src, uint2* __restrict__ dst, int npairs) {
    int i = blockIdx.x * blockDim.x + threadIdx.x;
    if (i >= npairs) return;
    float2 v = reinterpret_cast<const float2*>(src)[i];
    dst[permpos(i)] = packpair(v.x, v.y);
}

__global__ void k_gather_pack(const int* __restrict__ ids, const float* __restrict__ embed) {
    int gid = blockIdx.x * blockDim.x + threadIdx.x;
    const int total = NROWS * KPE;
    if (gid >= total) return;
    int r   = gid / KPE;
    int c   = gid % KPE;
    int s   = r / (TSTEP*BB);
    int rem = r % (TSTEP*BB);
    int t   = rem / BB;
    int b   = rem % BB;
    int tok = ids[(s*BB + b)*TT + t];
    float2 v = reinterpret_cast<const float2*>(embed + (size_t)tok*EE)[c];
    d_xp[(size_t)r*KPE + permpos(c)] = packpair(v.x, v.y);
}

// ---------------- staged big GEMM: C[3840, 3072] = A @ Bw^T + bias --------------
// CTA 128x128, 8 warps (2x4), warp 64x32. Tiles staged in smem via cp.async
// (2-stage double buffer); all warps read fragments from smem -> 3x less L2.
__global__ __launch_bounds__(256)
void k_mma_big(const uint2* __restrict__ A, const uint2* __restrict__ Bw,
               const float* __restrict__ bias, float* __restrict__ C, int Kp)
{
    __shared__ uint2 As[2][128*SRS];
    __shared__ uint2 Bs[2][128*SRS];

    int tid = threadIdx.x;
    int wid = tid >> 5, lane = tid & 31;
    int g = lane >> 2, tg = lane & 3;
    int wm = wid >> 2, wn = wid & 3;
    int m0c = blockIdx.x * 128;
    int n0c = blockIdx.y * 128;
    int wmL = wm * 64, wnL = wn * 32;

    unsigned int asB = (unsigned int)__cvta_generic_to_shared(As);
    unsigned int bsB = (unsigned int)__cvta_generic_to_shared(Bs);

    int lrow = tid >> 1;               // 0..127 (row this thread loads)
    int lch  = (tid & 1) * 2;          // chunk base 0 or 2 (each thread: 2 chunks)

    float acc[4][4][4];
#pragma unroll
    for (int mi = 0; mi < 4; mi++)
#pragma unroll
        for (int q = 0; q < 4; q++)
#pragma unroll
            for (int i = 0; i < 4; i++) acc[mi][q][i] = 0.0f;

    const int NIT = Kp >> 3;           // 8 pairs per stage

    // prologue: stage 0
    {
        const uint2* gA = A  + (size_t)(m0c + lrow)*Kp + lch*2;
        const uint2* gB = Bw + (size_t)(n0c + lrow)*Kp + lch*2;
        cpasync16(asB + (unsigned)((lrow*SRS + lch*2))*8, gA);
        cpasync16(asB + (unsigned)((lrow*SRS + lch*2 + 2))*8, gA + 2);
        cpasync16(bsB + (unsigned)((lrow*SRS + lch*2))*8, gB);
        cpasync16(bsB + (unsigned)((lrow*SRS + lch*2 + 2))*8, gB + 2);
    }
    cpcommit();

    for (int it = 0; it < NIT; it++) {
        int buf = it & 1;
        if (it + 1 < NIT) {
            int kc = (it + 1) << 3;
            int nb = buf ^ 1;
            const uint2* gA = A  + (size_t)(m0c + lrow)*Kp + kc + lch*2;
            const uint2* gB = Bw + (size_t)(n0c + lrow)*Kp + kc + lch*2;
            cpasync16(asB + (unsigned)(nb*128*SRS + lrow*SRS + lch*2)*8, gA);
            cpasync16(asB + (unsigned)(nb*128*SRS + lrow*SRS + lch*2 + 2)*8, gA + 2);
            cpasync16(bsB + (unsigned)(nb*128*SRS + lrow*SRS + lch*2)*8, gB);
            cpasync16(bsB + (unsigned)(nb*128*SRS + lrow*SRS + lch*2 + 2)*8, gB + 2);
        }
        cpcommit();
        cpwait1();
        __syncthreads();

        const uint2* as = As[buf];
        const uint2* bs = Bs[buf];
        uint4 a0[4], a1[4];
#pragma unroll
        for (int mi = 0; mi < 4; mi++) {
            a0[mi] = *(const uint4*)(as + (wmL + mi*16 + g    )*SRS + 2*tg);
            a1[mi] = *(const uint4*)(as + (wmL + mi*16 + g + 8)*SRS + 2*tg);
        }
#pragma unroll
        for (int q = 0; q < 4; q++) {
            uint4 vb = *(const uint4*)(bs + (wnL + 8*q + g)*SRS + 2*tg);
#pragma unroll
            for (int mi = 0; mi < 4; mi++)
                mma3v(acc[mi][q], a0[mi], a1[mi], vb);
        }
        __syncthreads();
    }

#pragma unroll
    for (int mi = 0; mi < 4; mi++) {
        int mA = m0c + wmL + mi*16 + g;
        int mB = mA + 8;
#pragma unroll
        for (int q = 0; q < 4; q++) {
            int col = n0c + wnL + 8*q + 2*tg;
            float b0v = bias[col], b1v = bias[col+1];
            *(float2*)(C + (size_t)mA*GG + col) = make_float2(acc[mi][q][0] + b0v, acc[mi][q][1] + b1v);
            *(float2*)(C + (size_t)mB*GG + col) = make_float2(acc[mi][q][2] + b0v, acc[mi][q][3] + b1v);
        }
    }
}

// ---------------- persistent single-layer recurrence (W cached in SMEM) ---------
__global__ __launch_bounds__(256, 1)
void k_recur(const uint2* __restrict__ W,      // [GG][KP] packed+permuted (W_hh)
             const float* __restrict__ gi,     // [NROWS][GG] input gates (+b_ih)
             const float* __restrict__ bias,   // [GG] b_hh
             float* __restrict__ hs,           // [NROWS][HH]
             uint2* __restrict__ hsp,          // [NROWS][KP] packed+permuted
             const int* __restrict__ lens)
{
    extern __shared__ uint2 Ws[];              // [24][WSTRIDE] weight slice
    __shared__ float Sp[8][24][33];            // per-warp gate partials
    __shared__ float hbuf[32*9];               // h outputs (padded)
    __shared__ const uint2* xptr[BB];          // per-batch packed hprev row
    __shared__ const float* hpv [BB];          // per-batch fp32 hprev row

    int tid  = threadIdx.x;
    int w    = tid >> 5, lane = tid & 31;
    int g    = lane >> 2, tg = lane & 3;
    int j0   = blockIdx.x * JT;
    int kb   = w * 64;                         // per-warp K chunk (uint2)

    // ---- one-time: copy this CTA's 24 gate rows into smem (layout preserved) ----
    for (int idx = tid; idx < 24*KP; idx += 256) {
        int r24 = idx >> 9;                    // 0..23
        int c   = idx & 511;
        int grow = (r24 < 8) ? (j0 + r24)
                 : (r24 < 16) ? (HH + j0 + (r24 - 8))
                 : (2*HH + j0 + (r24 - 16));
        Ws[r24*WSTRIDE + c] = W[(size_t)grow*KP + c];
    }
    __syncthreads();

    const uint2* WsR = Ws + (size_t)(g      ) * WSTRIDE;
    const uint2* WsZ = Ws + (size_t)(8 + g  ) * WSTRIDE;
    const uint2* WsN = Ws + (size_t)(16 + g ) * WSTRIDE;

    // pointwise mapping: thread -> (j = tid>>5, b = lane)
    int pj = tid >> 5, pb = lane;
    float bR = bias[j0 + pj];
    float bZ = bias[HH + j0 + pj];
    float bN = bias[2*HH + j0 + pj];

    for (int s = 0; s < SS; s++) {
        for (int t = 0; t < TSTEP; t++) {
            int step = s*TSTEP + t;

            // per-batch hprev row pointers (handles sentence carry + zero init)
            if (tid < BB) {
                int b = tid;
                const uint2* xp; const float* hp;
                if (t == 0) {
                    if (s == 0) { xp = d_zrow; hp = d_zf; }
                    else {
                        int idx = lens[(s-1)*BB + b] - 2;
                        idx = idx < 0 ? 0 : (idx > TSTEP-1 ? TSTEP-1 : idx);
                        size_t r = (size_t)((s-1)*TSTEP + idx)*BB + b;
                        xp = hsp + r*KP; hp = hs + r*HH;
                    }
                } else {
                    size_t r = (size_t)(step-1)*BB + b;
                    xp = hsp + r*KP; hp = hs + r*HH;
                }
                xptr[b] = xp; hpv[b] = hp;
            }
            __syncthreads();

            // ---- fused gate GEMM: W from smem (LDS.128), x from L2 (LDG.128) ----
            const uint2* x0 = xptr[g];
            const uint2* x1 = xptr[8+g];
            const uint2* x2 = xptr[16+g];
            const uint2* x3 = xptr[24+g];

            float acc0[4][4], acc1[4][4];
#pragma unroll
            for (int q = 0; q < 4; q++)
#pragma unroll
                for (int i = 0; i < 4; i++) { acc0[q][i] = 0.0f; acc1[q][i] = 0.0f; }

#pragma unroll
            for (int kk = 0; kk < 8; kk++) {
                int kc = kb + kk*8 + 2*tg;
                uint4 xb[4];
                xb[0] = *(const uint4*)(x0 + kc);
                xb[1] = *(const uint4*)(x1 + kc);
                xb[2] = *(const uint4*)(x2 + kc);
                xb[3] = *(const uint4*)(x3 + kc);

                uint4 vr = *(const uint4*)(WsR + kc);
                uint4 vz = *(const uint4*)(WsZ + kc);
                uint4 vn = *(const uint4*)(WsN + kc);
#pragma unroll
                for (int q = 0; q < 4; q++) {
                    mma3v(acc0[q], vr, vz, xb[q]);
                    mma3v(acc1[q], vn, vr, xb[q]);
                }
            }

            // store per-warp partials
#pragma unroll
            for (int q = 0; q < 4; q++) {
                int col = q*8 + 2*tg;
                Sp[w][g     ][col]   = acc0[q][0];
                Sp[w][g     ][col+1] = acc0[q][1];
                Sp[w][8 + g ][col]   = acc0[q][2];
                Sp[w][8 + g ][col+1] = acc0[q][3];
                Sp[w][16 + g][col]   = acc1[q][0];
                Sp[w][16 + g][col+1] = acc1[q][1];
            }
            __syncthreads();

            // ---- reduce 8 warps + GRU pointwise (one thread per (j,b)) ----
            {
                float sr = 0.f, sz = 0.f, sn = 0.f;
#pragma unroll
                for (int ww = 0; ww < 8; ww++) {
                    sr += Sp[ww][pj     ][pb];
                    sz += Sp[ww][8 + pj ][pb];
                    sn += Sp[ww][16 + pj][pb];
                }
                const float* gir = gi + ((size_t)step*BB + pb) * GG;
                float ir  = gir[j0 + pj];
                float iz  = gir[HH + j0 + pj];
                float inn = gir[2*HH + j0 + pj];
                float hprev = hpv[pb][j0 + pj];

                float rr = 1.0f / (1.0f + expf(-(ir + sr + bR)));
                float zz = 1.0f / (1.0f + expf(-(iz + sz + bZ)));
                float nn = tanhf(inn + rr * (sn + bN));
                hbuf[pb*9 + pj] = (1.0f - zz)*nn + zz*hprev;
            }
            __syncthreads();

            // ---- write h (fp32 + packed, permuted positions) ----
            {
                int b = tid >> 3, j = tid & 7;
                size_t row = (size_t)step*BB + b;
                hs[row*HH + j0 + j] = hbuf[b*9 + j];
            }
            if (tid < 128) {
                int b = tid >> 2, jp = tid & 3;
                size_t row = (size_t)step*BB + b;
                int p = (j0 >> 1) + jp;
                hsp[row*KP + permpos(p)] = packpair(hbuf[b*9 + 2*jp], hbuf[b*9 + 2*jp + 1]);
            }

            gbar();   // ONE global sync per step
        }
    }
}

// ---------------- staged logits GEMM: C[3840, 32000] = hs1 @ W_out^T ------------
__global__ __launch_bounds__(256)
void k_mma_logits(float* __restrict__ out)
{
    __shared__ uint2 As[2][128*SRS];
    __shared__ uint2 Bs[2][128*SRS];

    int tid = threadIdx.x;
    int wid = tid >> 5, lane = tid & 31;
    int g = lane >> 2, tg = lane & 3;
    int wm = wid >> 2, wn = wid & 3;
    int m0c = blockIdx.x * 128;
    int n0c = blockIdx.y * 128;
    int wmL = wm * 64, wnL = wn * 32;

    unsigned int asB = (unsigned int)__cvta_generic_to_shared(As);
    unsigned int bsB = (unsigned int)__cvta_generic_to_shared(Bs);

    int lrow = tid >> 1;
    int lch  = (tid & 1) * 2;

    float acc[4][4][4];
#pragma unroll
    for (int mi = 0; mi < 4; mi++)
#pragma unroll
        for (int q = 0; q < 4; q++)
#pragma unroll
            for (int i = 0; i < 4; i++) acc[mi][q][i] = 0.0f;

    const int NIT = KP >> 3;

    {
        const uint2* gA = d_hs1p + (size_t)(m0c + lrow)*KP + lch*2;
        const uint2* gB = d_WpO  + (size_t)(n0c + lrow)*KP + lch*2;
        cpasync16(asB + (unsigned)(lrow*SRS + lch*2)*8, gA);
        cpasync16(asB + (unsigned)(lrow*SRS + lch*2 + 2)*8, gA + 2);
        cpasync16(bsB + (unsigned)(lrow*SRS + lch*2)*8, gB);
        cpasync16(bsB + (unsigned)(lrow*SRS + lch*2 + 2)*8, gB + 2);
    }
    cpcommit();

    for (int it = 0; it < NIT; it++) {
        int buf = it & 1;
        if (it + 1 < NIT) {
            int kc = (it + 1) << 3;
            int nb = buf ^ 1;
            const uint2* gA = d_hs1p + (size_t)(m0c + lrow)*KP + kc + lch*2;
            const uint2* gB = d_WpO  + (size_t)(n0c + lrow)*KP + kc + lch*2;
            cpasync16(asB + (unsigned)(nb*128*SRS + lrow*SRS + lch*2)*8, gA);
            cpasync16(asB + (unsigned)(nb*128*SRS + lrow*SRS + lch*2 + 2)*8, gA + 2);
            cpasync16(bsB + (unsigned)(nb*128*SRS + lrow*SRS + lch*2)*8, gB);
            cpasync16(bsB + (unsigned)(nb*128*SRS + lrow*SRS + lch*2 + 2)*8, gB + 2);
        }
        cpcommit();
        cpwait1();
        __syncthreads();

        const uint2* as = As[buf];
        const uint2* bs = Bs[buf];
        uint4 a0[4], a1[4];
#pragma unroll
        for (int mi = 0; mi < 4; mi++) {
            a0[mi] = *(const uint4*)(as + (wmL + mi*16 + g    )*SRS + 2*tg);
            a1[mi] = *(const uint4*)(as + (wmL + mi*16 + g + 8)*SRS + 2*tg);
        }
#pragma unroll
        for (int q = 0; q < 4; q++) {
            uint4 vb = *(const uint4*)(bs + (wnL + 8*q + g)*SRS + 2*tg);
#pragma unroll
            for (int mi = 0; mi < 4; mi++)
                mma3v(acc[mi][q], a0[mi], a1[mi], vb);
        }
        __syncthreads();
    }

    // epilogue with (s,t,b)->(s,b,t) remap
#pragma unroll
    for (int mi = 0; mi < 4; mi++) {
        int mA = m0c + wmL + mi*16 + g;
        int mB = mA + 8;
        int sA = mA / (TSTEP*BB); int rA = mA % (TSTEP*BB);
        int sB = mB / (TSTEP*BB); int rB = mB % (TSTEP*BB);
        size_t rowA = ((size_t)(sA*BB + (rA % BB))*TSTEP + (rA / BB)) * VV;
        size_t rowB = ((size_t)(sB*BB + (rB % BB))*TSTEP + (rB / BB)) * VV;
#pragma unroll
        for (int q = 0; q < 4; q++) {
            int col = n0c + wnL + 8*q + 2*tg;
            *(float2*)(out + rowA + col) = make_float2(acc[mi][q][0], acc[mi][q][1]);
            *(float2*)(out + rowB + col) = make_float2(acc[mi][q][2], acc[mi][q][3]);
        }
    }
}

// ---------------- launcher ------------------------------------------------------
extern "C" void kernel_launch(void* const* d_in, const int* in_sizes, int n_in,
                              void* d_out, int out_size)
{
    (void)in_sizes; (void)n_in; (void)out_size;
    const int*   ids    = (const int*)  d_in[0];
    const int*   lens   = (const int*)  d_in[1];
    const float* embed  = (const float*)d_in[2];
    const float* W_ih0  = (const float*)d_in[3];
    const float* W_hh0  = (const float*)d_in[4];
    const float* b_ih0  = (const float*)d_in[5];
    const float* b_hh0  = (const float*)d_in[6];
    const float* W_ih1  = (const float*)d_in[7];
    const float* W_hh1  = (const float*)d_in[8];
    const float* b_ih1  = (const float*)d_in[9];
    const float* b_hh1  = (const float*)d_in[10];
    const float* W_out  = (const float*)d_in[11];
    float*       out    = (float*)d_out;

    uint2* wpi0; cudaGetSymbolAddress((void**)&wpi0, d_WpI0);
    uint2* wp0;  cudaGetSymbolAddress((void**)&wp0,  d_Wp0);
    uint2* wp1i; cudaGetSymbolAddress((void**)&wp1i, d_Wp1i);
    uint2* wp1h; cudaGetSymbolAddress((void**)&wp1h, d_Wp1h);
    uint2* wpo;  cudaGetSymbolAddress((void**)&wpo,  d_WpO);
    uint2* xp;   cudaGetSymbolAddress((void**)&xp,   d_xp);
    uint2* h0p;  cudaGetSymbolAddress((void**)&h0p,  d_hs0p);
    uint2* h1p;  cudaGetSymbolAddress((void**)&h1p,  d_hs1p);
    float* gi;   cudaGetSymbolAddress((void**)&gi,   d_gi);
    float* hs0;  cudaGetSymbolAddress((void**)&hs0,  d_hs0);
    float* hs1;  cudaGetSymbolAddress((void**)&hs1,  d_hs1);

    const int WS_BYTES = 24 * WSTRIDE * sizeof(uint2);   // 99,840 B
    cudaFuncSetAttribute(k_recur, cudaFuncAttributeMaxDynamicSharedMemorySize, WS_BYTES);

    // zero rows + gather/pack inputs (permuted layout)
    k_zero_init<<<1, 512>>>();
    k_gather_pack<<<(NROWS*KPE + 255)/256, 256>>>(ids, embed);
    k_packw<<<(GG*KPE + 255)/256, 256>>>(W_ih0, wpi0, GG*KPE);
    k_packw<<<(GG*KP  + 255)/256, 256>>>(W_hh0, wp0,  GG*KP);
    k_packw<<<(GG*KP  + 255)/256, 256>>>(W_ih1, wp1i, GG*KP);
    k_packw<<<(GG*KP  + 255)/256, 256>>>(W_hh1, wp1h, GG*KP);
    k_packw<<<(VV*KP  + 255)/256, 256>>>(W_out, wpo,  VV*KP);

    // gi(layer0) = x @ W_ih0^T + b_ih0
    k_mma_big<<<dim3(NROWS/128, GG/128), 256>>>(xp, wpi0, b_ih0, gi, KPE);

    // layer-0 recurrence (persistent, W in smem, 1 barrier/step)
    k_recur<<<NCTA, 256, WS_BYTES>>>(wp0, gi, b_hh0, hs0, h0p, lens);

    // gi(layer1) = h0_all @ W_ih1^T + b_ih1  (off critical path, one big GEMM)
    k_mma_big<<<dim3(NROWS/128, GG/128), 256>>>(h0p, wp1i, b_ih1, gi, KP);

    // layer-1 recurrence
    k_recur<<<NCTA, 256, WS_BYTES>>>(wp1h, gi, b_hh1, hs1, h1p, lens);

    // logits = hs1 @ W_out^T, remapped to (s, b, t, v)
    k_mma_logits<<<dim3(NROWS/128, VV/128), 256>>>(out);
}

// round 16
// speedup vs baseline: 1.1599x; 1.1599x over previous
#include <cuda_runtime.h>
#include <cuda_bf16.h>
#include <stdint.h>
#include <math.h>

// Problem constants
#define SS     5
#define BB     32
#define TT     25
#define TSTEP  24          // T-1 recurrence steps
#define VV     32000
#define EE     512
#define HH     1024
#define GG     3072        // 3*H
#define NROWS  (SS*TSTEP*BB)   // 3840
#define KP     (HH/2)      // 512 packed uint2 per row (hi-pair, lo-pair)
#define KPE    (EE/2)      // 256 packed uint2 per embedding row
#define NCTA   128         // persistent recurrence grid (1 CTA per 8 h-outputs)
#define JT     8           // h outputs per CTA
#define WSTRIDE 520        // smem row stride (uint2) for k_recur weight cache

// Pair-position permutation within each 8-pair group: slot -> (slot&3)*2 + (slot>>2).
// Puts pairs (tg, tg+4) adjacent so consumers use one 16B load per fragment pair.
__host__ __device__ __forceinline__ int permpos(int p) {
    int grp = p >> 3, slot = p & 7;
    return grp*8 + ((slot & 3)*2 + (slot >> 2));
}

// ---------------- scratch (static device globals; no allocation) ----------------
__device__ float d_gi  [(size_t)NROWS * GG];         // gi buffer (layer0, then layer1)
__device__ float d_hs0 [(size_t)NROWS * HH];         // layer0 hidden (fp32)
__device__ float d_hs1 [(size_t)NROWS * HH];         // layer1 hidden (fp32)

// packed split-bf16 (PERMUTED layout): uint2 {x = hi|hi<<16, y = lo|lo<<16}
__device__ uint2 d_xp  [(size_t)NROWS*KPE];          // embeddings packed
__device__ uint2 d_WpI0[(size_t)GG*KPE];             // W_ih0 packed
__device__ uint2 d_Wp0 [(size_t)GG*KP];              // W_hh0 packed
__device__ uint2 d_Wp1i[(size_t)GG*KP];              // W_ih1 packed
__device__ uint2 d_Wp1h[(size_t)GG*KP];              // W_hh1 packed
__device__ uint2 d_WpO [(size_t)VV*KP];              // W_out packed (131MB)
__device__ uint2 d_hs0p[(size_t)NROWS*KP];           // layer0 hidden packed
__device__ uint2 d_hs1p[(size_t)NROWS*KP];           // layer1 hidden packed
__device__ uint2 d_zrow[KP];                         // zero packed row
__device__ float d_zf  [HH];                         // zero fp32 row

// grid barrier state (separate lines)
__device__ unsigned d_cnt = 0;
__device__ unsigned d_padA[31];
__device__ unsigned d_gen = 0;

// ---------------- helpers -------------------------------------------------------
__device__ __forceinline__ uint2 packpair(float x, float y) {
    __nv_bfloat16 hx = __float2bfloat16_rn(x);
    __nv_bfloat16 hy = __float2bfloat16_rn(y);
    float rx = x - __bfloat162float(hx);
    float ry = y - __bfloat162float(hy);
    __nv_bfloat16 lx = __float2bfloat16_rn(rx);
    __nv_bfloat16 ly = __float2bfloat16_rn(ry);
    uint2 o;
    o.x = (unsigned int)__bfloat16_as_ushort(hx) | ((unsigned int)__bfloat16_as_ushort(hy) << 16);
    o.y = (unsigned int)__bfloat16_as_ushort(lx) | ((unsigned int)__bfloat16_as_ushort(ly) << 16);
    return o;
}

__device__ __forceinline__ void mma16816(float& d0, float& d1, float& d2, float& d3,
                                         unsigned int a0, unsigned int a1,
                                         unsigned int a2, unsigned int a3,
                                         unsigned int b0, unsigned int b1) {
    asm volatile(
        "mma.sync.aligned.m16n8k16.row.col.f32.bf16.bf16.f32 "
        "{%0,%1,%2,%3}, {%4,%5,%6,%7}, {%8,%9}, {%0,%1,%2,%3};\n"
        : "+f"(d0), "+f"(d1), "+f"(d2), "+f"(d3)
        : "r"(a0), "r"(a1), "r"(a2), "r"(a3), "r"(b0), "r"(b1));
}

// split-bf16 with uint4 fragments: v = {pair tg: hi,lo, pair tg+4: hi,lo} per row
// d += Ahi*Bhi + Ahi*Blo + Alo*Bhi
__device__ __forceinline__ void mma3v(float* d, uint4 v0, uint4 v1, uint4 vb) {
    mma16816(d[0], d[1], d[2], d[3], v0.x, v1.x, v0.z, v1.z, vb.x, vb.z);
    mma16816(d[0], d[1], d[2], d[3], v0.x, v1.x, v0.z, v1.z, vb.y, vb.w);
    mma16816(d[0], d[1], d[2], d[3], v0.y, v1.y, v0.w, v1.w, vb.x, vb.z);
}

// CG-style grid barrier: release-atomic arrive, acquire-poll on generation.
__device__ __forceinline__ void gbar() {
    __syncthreads();
    if (threadIdx.x == 0) {
        unsigned g;
        asm volatile("ld.relaxed.gpu.u32 %0, [%1];" : "=r"(g) : "l"(&d_gen));
        unsigned prev;
        asm volatile("atom.release.gpu.add.u32 %0, [%1], %2;"
                     : "=r"(prev) : "l"(&d_cnt), "r"(1u) : "memory");
        if (prev == NCTA - 1) {
            asm volatile("st.relaxed.gpu.u32 [%0], %1;" :: "l"(&d_cnt), "r"(0u) : "memory");
            asm volatile("st.release.gpu.u32 [%0], %1;" :: "l"(&d_gen), "r"(g + 1u) : "memory");
        } else {
            unsigned cur;
            do {
                asm volatile("ld.acquire.gpu.u32 %0, [%1];" : "=r"(cur) : "l"(&d_gen) : "memory");
            } while (cur == g);
        }
    }
    __syncthreads();
}

// ---------------- init / packing -----------------------------------------------
__global__ void k_zero_init() {
    int i = threadIdx.x;
    if (i < KP) d_zrow[i] = make_uint2(0u, 0u);
    d_zf[i] = 0.0f; d_zf[i + 512] = 0.0f;
}

// fused pack of the four recurrence/input weight matrices (one launch)
__global__ void k_pack4(const float* __restrict__ wih0, const float* __restrict__ whh0,
                        const float* __restrict__ wih1, const float* __restrict__ whh1)
{
    int i = blockIdx.x * blockDim.x + threadIdx.x;
    const int N0 = GG*KPE, N1 = GG*KP;
    const float* src; uint2* dst; int loc;
    if (i < N0)            { src = wih0; dst = d_WpI0; loc = i; }
    else if (i < N0 +   N1){ src = whh0; dst = d_Wp0;  loc = i - N0; }
    else if (i < N0 + 2*N1){ src = wih1; dst = d_Wp1i; loc = i - N0 - N1; }
    else if (i < N0 + 3*N1){ src = whh1; dst = d_Wp1h; loc = i - N0 - 2*N1; }
    else return;
    float2 v = reinterpret_cast<const float2*>(src)[loc];
    dst[permpos(loc)] = packpair(v.x, v.y);
}

// pack + permute W_out
__global__ void k_packw(const float* __restrict__ src, uint2* __restrict__ dst, int npairs) {
    int i = blockIdx.x * blockDim.x + threadIdx.x;
    if (i >= npairs) return;
    float2 v = reinterpret_cast<const float2*>(src)[i];
    dst[permpos(i)] = packpair(v.x, v.y);
}

__global__ void k_gather_pack(const int* __restrict__ ids, const float* __restrict__ embed) {
    int gid = blockIdx.x * blockDim.x + threadIdx.x;
    const int total = NROWS * KPE;
    if (gid >= total) return;
    int r   = gid / KPE;
    int c   = gid % KPE;
    int s   = r / (TSTEP*BB);
    int rem = r % (TSTEP*BB);
    int t   = rem / BB;
    int b   = rem % BB;
    int tok = ids[(s*BB + b)*TT + t];
    float2 v = reinterpret_cast<const float2*>(embed + (size_t)tok*EE)[c];
    d_xp[(size_t)r*KPE + permpos(c)] = packpair(v.x, v.y);
}

// ---------------- big GEMM: C[3840, 3072] = A @ Bw^T + bias ---------------------
// CTA 128x128, 8 warps (2x4), warp 64x32. Direct LDG.128 fragments.
// launch_bounds(256,2): cap regs at 128 -> 2 CTAs/SM for L2-latency hiding.
__global__ __launch_bounds__(256, 2)
void k_mma_big(const uint2* __restrict__ A, const uint2* __restrict__ Bw,
               const float* __restrict__ bias, float* __restrict__ C, int Kp)
{
    int wid = threadIdx.x >> 5, lane = threadIdx.x & 31;
    int g = lane >> 2, tg = lane & 3;
    int wm = wid >> 2, wn = wid & 3;
    int m0 = blockIdx.x * 128 + wm * 64;
    int n0 = blockIdx.y * 128 + wn * 32;

    float acc[4][4][4];
#pragma unroll
    for (int mi = 0; mi < 4; mi++)
#pragma unroll
        for (int q = 0; q < 4; q++)
#pragma unroll
            for (int i = 0; i < 4; i++) acc[mi][q][i] = 0.0f;

#pragma unroll 2
    for (int kc = 0; kc < Kp; kc += 8) {
        uint4 a0[4], a1[4];
#pragma unroll
        for (int mi = 0; mi < 4; mi++) {
            a0[mi] = *(const uint4*)(A + (size_t)(m0 + mi*16 + g    ) * Kp + kc + 2*tg);
            a1[mi] = *(const uint4*)(A + (size_t)(m0 + mi*16 + g + 8) * Kp + kc + 2*tg);
        }
#pragma unroll
        for (int q = 0; q < 4; q++) {
            uint4 vb = *(const uint4*)(Bw + (size_t)(n0 + 8*q + g) * Kp + kc + 2*tg);
#pragma unroll
            for (int mi = 0; mi < 4; mi++)
                mma3v(acc[mi][q], a0[mi], a1[mi], vb);
        }
    }

#pragma unroll
    for (int mi = 0; mi < 4; mi++) {
        int mA = m0 + mi*16 + g;
        int mB = mA + 8;
#pragma unroll
        for (int q = 0; q < 4; q++) {
            int col = n0 + 8*q + 2*tg;
            float b0v = bias[col], b1v = bias[col+1];
            *(float2*)(C + (size_t)mA*GG + col) = make_float2(acc[mi][q][0] + b0v, acc[mi][q][1] + b1v);
            *(float2*)(C + (size_t)mB*GG + col) = make_float2(acc[mi][q][2] + b0v, acc[mi][q][3] + b1v);
        }
    }
}

// ---------------- persistent single-layer recurrence (W cached in SMEM) ---------
__global__ __launch_bounds__(256, 1)
void k_recur(const uint2* __restrict__ W,      // [GG][KP] packed+permuted (W_hh)
             const float* __restrict__ gi,     // [NROWS][GG] input gates (+b_ih)
             const float* __restrict__ bias,   // [GG] b_hh
             float* __restrict__ hs,           // [NROWS][HH]
             uint2* __restrict__ hsp,          // [NROWS][KP] packed+permuted
             const int* __restrict__ lens)
{
    extern __shared__ uint2 Ws[];              // [24][WSTRIDE] weight slice
    __shared__ float Sp[8][24][33];            // per-warp gate partials
    __shared__ float hbuf[32*9];               // h outputs (padded)
    __shared__ const uint2* xptr[BB];          // per-batch packed hprev row
    __shared__ const float* hpv [BB];          // per-batch fp32 hprev row

    int tid  = threadIdx.x;
    int w    = tid >> 5, lane = tid & 31;
    int g    = lane >> 2, tg = lane & 3;
    int j0   = blockIdx.x * JT;
    int kb   = w * 64;                         // per-warp K chunk (uint2)

    // ---- one-time: copy this CTA's 24 gate rows into smem (layout preserved) ----
    for (int idx = tid; idx < 24*KP; idx += 256) {
        int r24 = idx >> 9;                    // 0..23
        int c   = idx & 511;
        int grow = (r24 < 8) ? (j0 + r24)
                 : (r24 < 16) ? (HH + j0 + (r24 - 8))
                 : (2*HH + j0 + (r24 - 16));
        Ws[r24*WSTRIDE + c] = W[(size_t)grow*KP + c];
    }
    __syncthreads();

    const uint2* WsR = Ws + (size_t)(g      ) * WSTRIDE;
    const uint2* WsZ = Ws + (size_t)(8 + g  ) * WSTRIDE;
    const uint2* WsN = Ws + (size_t)(16 + g ) * WSTRIDE;

    // pointwise mapping: thread -> (j = tid>>5, b = lane)
    int pj = tid >> 5, pb = lane;
    float bR = bias[j0 + pj];
    float bZ = bias[HH + j0 + pj];
    float bN = bias[2*HH + j0 + pj];

    for (int s = 0; s < SS; s++) {
        for (int t = 0; t < TSTEP; t++) {
            int step = s*TSTEP + t;

            // per-batch hprev row pointers (handles sentence carry + zero init)
            if (tid < BB) {
                int b = tid;
                const uint2* xp; const float* hp;
                if (t == 0) {
                    if (s == 0) { xp = d_zrow; hp = d_zf; }
                    else {
                        int idx = lens[(s-1)*BB + b] - 2;
                        idx = idx < 0 ? 0 : (idx > TSTEP-1 ? TSTEP-1 : idx);
                        size_t r = (size_t)((s-1)*TSTEP + idx)*BB + b;
                        xp = hsp + r*KP; hp = hs + r*HH;
                    }
                } else {
                    size_t r = (size_t)(step-1)*BB + b;
                    xp = hsp + r*KP; hp = hs + r*HH;
                }
                xptr[b] = xp; hpv[b] = hp;
            }
            __syncthreads();

            // ---- fused gate GEMM: W from smem (LDS.128), x from L2 (LDG.128) ----
            const uint2* x0 = xptr[g];
            const uint2* x1 = xptr[8+g];
            const uint2* x2 = xptr[16+g];
            const uint2* x3 = xptr[24+g];

            float acc0[4][4], acc1[4][4];
#pragma unroll
            for (int q = 0; q < 4; q++)
#pragma unroll
                for (int i = 0; i < 4; i++) { acc0[q][i] = 0.0f; acc1[q][i] = 0.0f; }

#pragma unroll
            for (int kk = 0; kk < 8; kk++) {
                int kc = kb + kk*8 + 2*tg;
                uint4 xb[4];
                xb[0] = *(const uint4*)(x0 + kc);
                xb[1] = *(const uint4*)(x1 + kc);
                xb[2] = *(const uint4*)(x2 + kc);
                xb[3] = *(const uint4*)(x3 + kc);

                uint4 vr = *(const uint4*)(WsR + kc);
                uint4 vz = *(const uint4*)(WsZ + kc);
                uint4 vn = *(const uint4*)(WsN + kc);
#pragma unroll
                for (int q = 0; q < 4; q++) {
                    mma3v(acc0[q], vr, vz, xb[q]);
                    mma3v(acc1[q], vn, vr, xb[q]);
                }
            }

            // store per-warp partials
#pragma unroll
            for (int q = 0; q < 4; q++) {
                int col = q*8 + 2*tg;
                Sp[w][g     ][col]   = acc0[q][0];
                Sp[w][g     ][col+1] = acc0[q][1];
                Sp[w][8 + g ][col]   = acc0[q][2];
                Sp[w][8 + g ][col+1] = acc0[q][3];
                Sp[w][16 + g][col]   = acc1[q][0];
                Sp[w][16 + g][col+1] = acc1[q][1];
            }
            __syncthreads();

            // ---- reduce 8 warps + GRU pointwise (one thread per (j,b)) ----
            {
                float sr = 0.f, sz = 0.f, sn = 0.f;
#pragma unroll
                for (int ww = 0; ww < 8; ww++) {
                    sr += Sp[ww][pj     ][pb];
                    sz += Sp[ww][8 + pj ][pb];
                    sn += Sp[ww][16 + pj][pb];
                }
                const float* gir = gi + ((size_t)step*BB + pb) * GG;
                float ir  = gir[j0 + pj];
                float iz  = gir[HH + j0 + pj];
                float inn = gir[2*HH + j0 + pj];
                float hprev = hpv[pb][j0 + pj];

                float rr = 1.0f / (1.0f + expf(-(ir + sr + bR)));
                float zz = 1.0f / (1.0f + expf(-(iz + sz + bZ)));
                float nn = tanhf(inn + rr * (sn + bN));
                hbuf[pb*9 + pj] = (1.0f - zz)*nn + zz*hprev;
            }
            __syncthreads();

            // ---- write h (fp32 + packed, permuted positions) ----
            {
                int b = tid >> 3, j = tid & 7;
                size_t row = (size_t)step*BB + b;
                hs[row*HH + j0 + j] = hbuf[b*9 + j];
            }
            if (tid < 128) {
                int b = tid >> 2, jp = tid & 3;
                size_t row = (size_t)step*BB + b;
                int p = (j0 >> 1) + jp;
                hsp[row*KP + permpos(p)] = packpair(hbuf[b*9 + 2*jp], hbuf[b*9 + 2*jp + 1]);
            }

            gbar();   // ONE global sync per step
        }
    }
}

// ---------------- logits GEMM: C[3840, 32000] = hs1 @ W_out^T -------------------
__global__ __launch_bounds__(256, 2)
void k_mma_logits(float* __restrict__ out)
{
    int wid = threadIdx.x >> 5, lane = threadIdx.x & 31;
    int g = lane >> 2, tg = lane & 3;
    int wm = wid >> 2, wn = wid & 3;
    int m0 = blockIdx.x * 128 + wm * 64;
    int n0 = blockIdx.y * 128 + wn * 32;

    float acc[4][4][4];
#pragma unroll
    for (int mi = 0; mi < 4; mi++)
#pragma unroll
        for (int q = 0; q < 4; q++)
#pragma unroll
            for (int i = 0; i < 4; i++) acc[mi][q][i] = 0.0f;

#pragma unroll 2
    for (int kc = 0; kc < KP; kc += 8) {
        uint4 a0[4], a1[4];
#pragma unroll
        for (int mi = 0; mi < 4; mi++) {
            a0[mi] = *(const uint4*)(d_hs1p + (size_t)(m0 + mi*16 + g    ) * KP + kc + 2*tg);
            a1[mi] = *(const uint4*)(d_hs1p + (size_t)(m0 + mi*16 + g + 8) * KP + kc + 2*tg);
        }
#pragma unroll
        for (int q = 0; q < 4; q++) {
            uint4 vb = *(const uint4*)(d_WpO + (size_t)(n0 + 8*q + g) * KP + kc + 2*tg);
#pragma unroll
            for (int mi = 0; mi < 4; mi++)
                mma3v(acc[mi][q], a0[mi], a1[mi], vb);
        }
    }

    // epilogue with (s,t,b)->(s,b,t) remap
#pragma unroll
    for (int mi = 0; mi < 4; mi++) {
        int mA = m0 + mi*16 + g;
        int mB = mA + 8;
        int sA = mA / (TSTEP*BB); int rA = mA % (TSTEP*BB);
        int sB = mB / (TSTEP*BB); int rB = mB % (TSTEP*BB);
        size_t rowA = ((size_t)(sA*BB + (rA % BB))*TSTEP + (rA / BB)) * VV;
        size_t rowB = ((size_t)(sB*BB + (rB % BB))*TSTEP + (rB / BB)) * VV;
#pragma unroll
        for (int q = 0; q < 4; q++) {
            int col = n0 + 8*q + 2*tg;
            *(float2*)(out + rowA + col) = make_float2(acc[mi][q][0], acc[mi][q][1]);
            *(float2*)(out + rowB + col) = make_float2(acc[mi][q][2], acc[mi][q][3]);
        }
    }
}

// ---------------- launcher ------------------------------------------------------
extern "C" void kernel_launch(void* const* d_in, const int* in_sizes, int n_in,
                              void* d_out, int out_size)
{
    (void)in_sizes; (void)n_in; (void)out_size;
    const int*   ids    = (const int*)  d_in[0];
    const int*   lens   = (const int*)  d_in[1];
    const float* embed  = (const float*)d_in[2];
    const float* W_ih0  = (const float*)d_in[3];
    const float* W_hh0  = (const float*)d_in[4];
    const float* b_ih0  = (const float*)d_in[5];
    const float* b_hh0  = (const float*)d_in[6];
    const float* W_ih1  = (const float*)d_in[7];
    const float* W_hh1  = (const float*)d_in[8];
    const float* b_ih1  = (const float*)d_in[9];
    const float* b_hh1  = (const float*)d_in[10];
    const float* W_out  = (const float*)d_in[11];
    float*       out    = (float*)d_out;

    uint2* wpi0; cudaGetSymbolAddress((void**)&wpi0, d_WpI0);
    uint2* wp0;  cudaGetSymbolAddress((void**)&wp0,  d_Wp0);
    uint2* wp1i; cudaGetSymbolAddress((void**)&wp1i, d_Wp1i);
    uint2* wp1h; cudaGetSymbolAddress((void**)&wp1h, d_Wp1h);
    uint2* wpo;  cudaGetSymbolAddress((void**)&wpo,  d_WpO);
    uint2* xp;   cudaGetSymbolAddress((void**)&xp,   d_xp);
    uint2* h0p;  cudaGetSymbolAddress((void**)&h0p,  d_hs0p);
    uint2* h1p;  cudaGetSymbolAddress((void**)&h1p,  d_hs1p);
    float* gi;   cudaGetSymbolAddress((void**)&gi,   d_gi);
    float* hs0;  cudaGetSymbolAddress((void**)&hs0,  d_hs0);
    float* hs1;  cudaGetSymbolAddress((void**)&hs1,  d_hs1);

    const int WS_BYTES = 24 * WSTRIDE * sizeof(uint2);   // 99,840 B
    cudaFuncSetAttribute(k_recur, cudaFuncAttributeMaxDynamicSharedMemorySize, WS_BYTES);

    // #1 zero rows, #2 gather/pack embeddings
    k_zero_init<<<1, 512>>>();
    k_gather_pack<<<(NROWS*KPE + 255)/256, 256>>>(ids, embed);

    // #3 fused pack of the four GG weight matrices
    const int NP4 = GG*KPE + 3*GG*KP;
    k_pack4<<<(NP4 + 255)/256, 256>>>(W_ih0, W_hh0, W_ih1, W_hh1);

    // #4 pack W_out
    k_packw<<<(VV*KP + 255)/256, 256>>>(W_out, wpo, VV*KP);

    // #5 gi(layer0) = x @ W_ih0^T + b_ih0
    k_mma_big<<<dim3(NROWS/128, GG/128), 256>>>(xp, wpi0, b_ih0, gi, KPE);

    // #6 layer-0 recurrence  (<- ncu -s 5 -c 1 profiles THIS launch)
    k_recur<<<NCTA, 256, WS_BYTES>>>(wp0, gi, b_hh0, hs0, h0p, lens);

    // #7 gi(layer1) = h0_all @ W_ih1^T + b_ih1
    k_mma_big<<<dim3(NROWS/128, GG/128), 256>>>(h0p, wp1i, b_ih1, gi, KP);

    // #8 layer-1 recurrence
    k_recur<<<NCTA, 256, WS_BYTES>>>(wp1h, gi, b_hh1, hs1, h1p, lens);

    // #9 logits = hs1 @ W_out^T, remapped to (s, b, t, v)
    k_mma_logits<<<dim3(NROWS/128, VV/128), 256>>>(out);
}